// round 5
// baseline (speedup 1.0000x reference)
#include <cuda_runtime.h>
#include <cuda_bf16.h>
#include <cstdint>

// out[t][o] = sum_h R[t][h] * W[o][h],  R = x @ basis^T, W = amp*cos(phase)
// Fused: one CTA owns 128 tokens. Phase 1 computes R in-CTA (HMMA, 3-term
// bf16 split) straight into the A smem tile; phase 2 sweeps all 32 W-tiles.
//   A = [R_hi | R_lo | R_hi] (K=96), B = [W_hi | W_hi | W_lo]
#define TOKENS 16384
#define INF    1024
#define HARM   32
#define OUTF   4096
#define KSPL   96
#define KPAD   120   // A/B smem row stride in bf16 (240 B)
#define RPAD   72    // phase-1 staging row stride in bf16

// Scratch device globals
__device__ __align__(16) __nv_bfloat16 g_Ws[OUTF * KSPL];    // 768 KB [o][hi|hi|lo]
__device__ __align__(16) __nv_bfloat16 g_Bh[HARM * INF];     // 64 KB basis hi
__device__ __align__(16) __nv_bfloat16 g_Bl[HARM * INF];     // 64 KB basis lo

__device__ __forceinline__ uint32_t smem_u32(const void* p) {
    uint32_t a;
    asm("{ .reg .u64 t; cvta.to.shared.u64 t, %1; cvt.u32.u64 %0, t; }"
        : "=r"(a) : "l"(p));
    return a;
}
__device__ __forceinline__ uint32_t pack_bf2(__nv_bfloat16 a, __nv_bfloat16 b) {
    return (uint32_t)__bfloat16_as_ushort(a) |
           ((uint32_t)__bfloat16_as_ushort(b) << 16);
}

// ---------------------------------------------------------------------------
// Prep: W = amp*cos(phase) split [o][hi|hi|lo]; basis split hi/lo.
// ---------------------------------------------------------------------------
__global__ void prep_kernel(const float* __restrict__ phase,
                            const float* __restrict__ amp,
                            const float* __restrict__ basis) {
    int idx = blockIdx.x * 256 + threadIdx.x;
    if (idx < OUTF * HARM) {
        int o = idx >> 5;
        int h = idx & 31;
        float w = amp[idx] * cosf(phase[idx]);
        __nv_bfloat16 hi = __float2bfloat16(w);
        __nv_bfloat16 lo = __float2bfloat16(w - __bfloat162float(hi));
        g_Ws[o * KSPL + h]      = hi;
        g_Ws[o * KSPL + 32 + h] = hi;
        g_Ws[o * KSPL + 64 + h] = lo;
    } else {
        int b = idx - OUTF * HARM;
        if (b < HARM * INF) {
            float v = basis[b];
            __nv_bfloat16 hi = __float2bfloat16(v);
            __nv_bfloat16 lo = __float2bfloat16(v - __bfloat162float(hi));
            g_Bh[b] = hi;
            g_Bl[b] = lo;
        }
    }
}

// ---------------------------------------------------------------------------
// Fused kernel. Grid = 128 CTAs x 256 threads (8 warps = 2(m) x 4(n) in ph2).
// SMEM map (dynamic, 92160 B):
//   sA  [0, 30720)            : A tile 128 x KPAD bf16 (split R)
//   sB0 [30720, 61440)        : B tile double-buffer 0
//   sB1 [61440, 92160)        : B tile double-buffer 1
//   phase-1 staging aliases sB region:
//     sxh @30720 (18432), sxl @49152 (18432), sbh @67584 (4608), sbl @72192 (4608)
// ---------------------------------------------------------------------------
#define OFF_A   0
#define OFF_B0  30720
#define OFF_B1  61440
#define OFF_XH  30720
#define OFF_XL  49152
#define OFF_BH  67584
#define OFF_BL  72192
#define SMF_TOTAL 92160
#define WSTRIDE 40

__global__ __launch_bounds__(256) void holo_fused_kernel(
    const float* __restrict__ x, float* __restrict__ out) {
    extern __shared__ char smem[];
    __shared__ float wstage[8][16 * WSTRIDE];

    int tid  = threadIdx.x;
    int lane = tid & 31;
    int wid  = tid >> 5;
    int tb   = blockIdx.x * 128;

    uint32_t sbase = smem_u32(smem);
    __nv_bfloat16* sA  = reinterpret_cast<__nv_bfloat16*>(smem + OFF_A);
    __nv_bfloat16* sxh = reinterpret_cast<__nv_bfloat16*>(smem + OFF_XH);
    __nv_bfloat16* sxl = reinterpret_cast<__nv_bfloat16*>(smem + OFF_XL);
    __nv_bfloat16* sbh = reinterpret_cast<__nv_bfloat16*>(smem + OFF_BH);
    __nv_bfloat16* sbl = reinterpret_cast<__nv_bfloat16*>(smem + OFF_BL);

    int qrow = lane >> 2;          // 0..7
    int qcol = (lane & 3) * 2;     // 0,2,4,6

    // ======================= Phase 1: R = x @ basis^T ======================
    {
        uint32_t sxh_b = sbase + OFF_XH, sxl_b = sbase + OFF_XL;
        uint32_t sbh_b = sbase + OFF_BH, sbl_b = sbase + OFF_BL;

        float acc[4][4];
#pragma unroll
        for (int j = 0; j < 4; j++)
#pragma unroll
            for (int c = 0; c < 4; c++) acc[j][c] = 0.0f;

        const float4* gx  = reinterpret_cast<const float4*>(x);
        const uint4*  gbh = reinterpret_cast<const uint4*>(g_Bh);
        const uint4*  gbl = reinterpret_cast<const uint4*>(g_Bl);

        float4 xp[8];
        uint4  bhp, blp;
        // prefetch chunk 0
#pragma unroll
        for (int r = 0; r < 8; r++) {
            int q = tid + r * 256;              // 0..2047
            int row = q >> 4, c4 = q & 15;
            xp[r] = gx[(long)(tb + row) * 256 + c4];
        }
        {
            int row = tid >> 3, c4 = tid & 7;   // 32 rows x 8 chunks
            bhp = gbh[row * 128 + c4];
            blp = gbl[row * 128 + c4];
        }

        for (int ck = 0; ck < 16; ck++) {
            if (ck > 0) __syncthreads();
#pragma unroll
            for (int r = 0; r < 8; r++) {
                int q = tid + r * 256;
                int row = q >> 4, c4 = q & 15;
                float4 v = xp[r];
                __nv_bfloat16 h0 = __float2bfloat16(v.x);
                __nv_bfloat16 h1 = __float2bfloat16(v.y);
                __nv_bfloat16 h2 = __float2bfloat16(v.z);
                __nv_bfloat16 h3 = __float2bfloat16(v.w);
                uint2 hp = make_uint2(pack_bf2(h0, h1), pack_bf2(h2, h3));
                uint2 lp = make_uint2(
                    pack_bf2(__float2bfloat16(v.x - __bfloat162float(h0)),
                             __float2bfloat16(v.y - __bfloat162float(h1))),
                    pack_bf2(__float2bfloat16(v.z - __bfloat162float(h2)),
                             __float2bfloat16(v.w - __bfloat162float(h3))));
                int off = row * RPAD + c4 * 4;
                *reinterpret_cast<uint2*>(&sxh[off]) = hp;
                *reinterpret_cast<uint2*>(&sxl[off]) = lp;
            }
            {
                int row = tid >> 3, c4 = tid & 7;
                int off = row * RPAD + c4 * 8;
                *reinterpret_cast<uint4*>(&sbh[off]) = bhp;
                *reinterpret_cast<uint4*>(&sbl[off]) = blp;
            }
            __syncthreads();

            if (ck < 15) {
                int kc4 = (ck + 1) * 16;
#pragma unroll
                for (int r = 0; r < 8; r++) {
                    int q = tid + r * 256;
                    int row = q >> 4, c4 = q & 15;
                    xp[r] = gx[(long)(tb + row) * 256 + kc4 + c4];
                }
                int row = tid >> 3, c4 = tid & 7;
                bhp = gbh[row * 128 + (ck + 1) * 8 + c4];
                blp = gbl[row * 128 + (ck + 1) * 8 + c4];
            }

#pragma unroll
            for (int ks = 0; ks < 4; ks++) {
                int k0 = ks * 16;
                uint32_t ah[4], al[4];
                {
                    int row = wid * 16 + (lane & 15);
                    uint32_t ao = (uint32_t)row * (RPAD * 2) + k0 * 2 + (lane >> 4) * 16;
                    asm volatile(
                        "ldmatrix.sync.aligned.m8n8.x4.shared.b16 {%0,%1,%2,%3}, [%4];"
                        : "=r"(ah[0]), "=r"(ah[1]), "=r"(ah[2]), "=r"(ah[3])
                        : "r"(sxh_b + ao));
                    asm volatile(
                        "ldmatrix.sync.aligned.m8n8.x4.shared.b16 {%0,%1,%2,%3}, [%4];"
                        : "=r"(al[0]), "=r"(al[1]), "=r"(al[2]), "=r"(al[3])
                        : "r"(sxl_b + ao));
                }
#pragma unroll
                for (int j = 0; j < 4; j++) {
                    int nrow = j * 8 + (lane & 7);
                    uint32_t bo = (uint32_t)nrow * (RPAD * 2) + k0 * 2 + ((lane >> 3) & 1) * 16;
                    uint32_t bh[2], bl[2];
                    asm volatile(
                        "ldmatrix.sync.aligned.m8n8.x2.shared.b16 {%0,%1}, [%2];"
                        : "=r"(bh[0]), "=r"(bh[1]) : "r"(sbh_b + bo));
                    asm volatile(
                        "ldmatrix.sync.aligned.m8n8.x2.shared.b16 {%0,%1}, [%2];"
                        : "=r"(bl[0]), "=r"(bl[1]) : "r"(sbl_b + bo));
                    asm volatile(
                        "mma.sync.aligned.m16n8k16.row.col.f32.bf16.bf16.f32 "
                        "{%0,%1,%2,%3}, {%4,%5,%6,%7}, {%8,%9}, {%0,%1,%2,%3};"
                        : "+f"(acc[j][0]), "+f"(acc[j][1]), "+f"(acc[j][2]), "+f"(acc[j][3])
                        : "r"(ah[0]), "r"(ah[1]), "r"(ah[2]), "r"(ah[3]),
                          "r"(bh[0]), "r"(bh[1]));
                    asm volatile(
                        "mma.sync.aligned.m16n8k16.row.col.f32.bf16.bf16.f32 "
                        "{%0,%1,%2,%3}, {%4,%5,%6,%7}, {%8,%9}, {%0,%1,%2,%3};"
                        : "+f"(acc[j][0]), "+f"(acc[j][1]), "+f"(acc[j][2]), "+f"(acc[j][3])
                        : "r"(al[0]), "r"(al[1]), "r"(al[2]), "r"(al[3]),
                          "r"(bh[0]), "r"(bh[1]));
                    asm volatile(
                        "mma.sync.aligned.m16n8k16.row.col.f32.bf16.bf16.f32 "
                        "{%0,%1,%2,%3}, {%4,%5,%6,%7}, {%8,%9}, {%0,%1,%2,%3};"
                        : "+f"(acc[j][0]), "+f"(acc[j][1]), "+f"(acc[j][2]), "+f"(acc[j][3])
                        : "r"(ah[0]), "r"(ah[1]), "r"(ah[2]), "r"(ah[3]),
                          "r"(bl[0]), "r"(bl[1]));
                }
            }
        }
        __syncthreads();   // phase-1 smem reads done before A-tile write overlap

        // Write split R into sA: [t][hi(0:32) | lo(32:64) | hi(64:96)]
        uint32_t* sA32 = reinterpret_cast<uint32_t*>(sA);
#pragma unroll
        for (int j = 0; j < 4; j++) {
            int wc = (j * 8 + qcol) >> 1;   // u32 col 0..15
#pragma unroll
            for (int hh = 0; hh < 2; hh++) {
                int row = wid * 16 + qrow + hh * 8;
                float v0 = acc[j][hh * 2 + 0];
                float v1 = acc[j][hh * 2 + 1];
                __nv_bfloat16 h0 = __float2bfloat16(v0);
                __nv_bfloat16 h1 = __float2bfloat16(v1);
                uint32_t hip = pack_bf2(h0, h1);
                uint32_t lop = pack_bf2(
                    __float2bfloat16(v0 - __bfloat162float(h0)),
                    __float2bfloat16(v1 - __bfloat162float(h1)));
                int base = row * (KPAD / 2);
                sA32[base + wc]      = hip;
                sA32[base + 16 + wc] = lop;
                sA32[base + 32 + wc] = hip;
            }
        }
    }

    // ======================= Phase 2: out = A @ W^T ========================
    int warp_m = wid >> 2;   // 0..1
    int warp_n = wid & 3;    // 0..3
    uint32_t sAb = sbase + OFF_A;
    const uint4* gW = reinterpret_cast<const uint4*>(g_Ws);

    // prefetch B tile 0
    uint4 bq[6];
#pragma unroll
    for (int r = 0; r < 6; r++) {
        int q = tid + r * 256;         // 0..1535
        int row = q / 12, ch = q - row * 12;
        bq[r] = gW[(long)row * 12 + ch];
    }
    __syncthreads();                   // A tile + phase-1 staging reads complete
#pragma unroll
    for (int r = 0; r < 6; r++) {
        int q = tid + r * 256;
        int row = q / 12, ch = q - row * 12;
        *reinterpret_cast<uint4*>(smem + OFF_B0 + row * (KPAD * 2) + ch * 16) = bq[r];
    }
    __syncthreads();

    for (int ob = 0; ob < 32; ob++) {
        uint32_t sBb = sbase + ((ob & 1) ? OFF_B1 : OFF_B0);

        if (ob < 31) {
#pragma unroll
            for (int r = 0; r < 6; r++) {
                int q = tid + r * 256;
                int row = q / 12, ch = q - row * 12;
                bq[r] = gW[(long)((ob + 1) * 128 + row) * 12 + ch];
            }
        }

        float acc[4][4][4];
#pragma unroll
        for (int i = 0; i < 4; i++)
#pragma unroll
            for (int j = 0; j < 4; j++)
#pragma unroll
                for (int c = 0; c < 4; c++) acc[i][j][c] = 0.0f;

#pragma unroll
        for (int ks = 0; ks < 6; ks++) {
            int k0 = ks * 16;
            uint32_t af[4][4];
#pragma unroll
            for (int i = 0; i < 4; i++) {
                int row = warp_m * 64 + i * 16 + (lane & 15);
                uint32_t addr = sAb + (uint32_t)row * (KPAD * 2) + k0 * 2 + (lane >> 4) * 16;
                asm volatile(
                    "ldmatrix.sync.aligned.m8n8.x4.shared.b16 {%0,%1,%2,%3}, [%4];"
                    : "=r"(af[i][0]), "=r"(af[i][1]), "=r"(af[i][2]), "=r"(af[i][3])
                    : "r"(addr));
            }
            uint32_t bf[4][2];
#pragma unroll
            for (int j = 0; j < 4; j++) {
                int nrow = warp_n * 32 + j * 8 + (lane & 7);
                uint32_t addr = sBb + (uint32_t)nrow * (KPAD * 2) + k0 * 2 + ((lane >> 3) & 1) * 16;
                asm volatile(
                    "ldmatrix.sync.aligned.m8n8.x2.shared.b16 {%0,%1}, [%2];"
                    : "=r"(bf[j][0]), "=r"(bf[j][1])
                    : "r"(addr));
            }
#pragma unroll
            for (int i = 0; i < 4; i++)
#pragma unroll
                for (int j = 0; j < 4; j++) {
                    asm volatile(
                        "mma.sync.aligned.m16n8k16.row.col.f32.bf16.bf16.f32 "
                        "{%0,%1,%2,%3}, {%4,%5,%6,%7}, {%8,%9}, {%0,%1,%2,%3};"
                        : "+f"(acc[i][j][0]), "+f"(acc[i][j][1]),
                          "+f"(acc[i][j][2]), "+f"(acc[i][j][3])
                        : "r"(af[i][0]), "r"(af[i][1]), "r"(af[i][2]), "r"(af[i][3]),
                          "r"(bf[j][0]), "r"(bf[j][1]));
                }
        }

        // Staged epilogue: per-warp 16x32 tile through smem -> STG.128.
        float* wb = wstage[wid];
#pragma unroll
        for (int i = 0; i < 4; i++) {
#pragma unroll
            for (int j = 0; j < 4; j++) {
                *reinterpret_cast<float2*>(&wb[qrow * WSTRIDE + j * 8 + qcol]) =
                    make_float2(acc[i][j][0], acc[i][j][1]);
                *reinterpret_cast<float2*>(&wb[(qrow + 8) * WSTRIDE + j * 8 + qcol]) =
                    make_float2(acc[i][j][2], acc[i][j][3]);
            }
            __syncwarp();
            long r0 = tb + warp_m * 64 + i * 16;
            long c0 = (long)ob * 128 + warp_n * 32;
#pragma unroll
            for (int s = 0; s < 4; s++) {
                int q = lane + s * 32;       // 0..127
                int row = q >> 3, c4 = q & 7;
                float4 v = *reinterpret_cast<float4*>(&wb[row * WSTRIDE + c4 * 4]);
                *reinterpret_cast<float4*>(&out[(r0 + row) * OUTF + c0 + c4 * 4]) = v;
            }
            __syncwarp();
        }

        if (ob < 31) {
            uint32_t dstb = (ob & 1) ? OFF_B0 : OFF_B1;
#pragma unroll
            for (int r = 0; r < 6; r++) {
                int q = tid + r * 256;
                int row = q / 12, ch = q - row * 12;
                *reinterpret_cast<uint4*>(smem + dstb + row * (KPAD * 2) + ch * 16) = bq[r];
            }
            __syncthreads();
        }
    }
}

// ---------------------------------------------------------------------------
extern "C" void kernel_launch(void* const* d_in, const int* in_sizes, int n_in,
                              void* d_out, int out_size) {
    const float* x     = (const float*)d_in[0];  // [16384,1024]
    const float* basis = (const float*)d_in[1];  // [32,1024]
    const float* phase = (const float*)d_in[2];  // [4096,32]
    const float* amp   = (const float*)d_in[3];  // [4096,32]
    float* out = (float*)d_out;                  // [16384,4096]

    cudaFuncSetAttribute(holo_fused_kernel,
                         cudaFuncAttributeMaxDynamicSharedMemorySize, SMF_TOTAL);

    int prep_items = OUTF * HARM + HARM * INF;
    prep_kernel<<<(prep_items + 255) / 256, 256>>>(phase, amp, basis);
    holo_fused_kernel<<<TOKENS / 128, 256, SMF_TOTAL>>>(x, out);
}

// round 6
// speedup vs baseline: 1.3123x; 1.3123x over previous
#include <cuda_runtime.h>
#include <cuda_bf16.h>
#include <cstdint>

// out[t][o] = sum_h R[t][h] * W[o][h],  R = x @ basis^T, W = amp*cos(phase)
// Step 2 (R): HMMA bf16 3-term split (error ~1e-5).
// Step 3 (out): mma.m16n8k8 TF32, single term K=32 (error ~4e-4 < 1e-3).
#define TOKENS 16384
#define INF    1024
#define HARM   32
#define OUTF   4096
#define RPAD   72    // step-2 staging row stride in bf16

// Scratch device globals
__device__ __align__(16) float g_R[TOKENS * HARM];   // 2 MB, tf32-rounded fp32
__device__ __align__(16) float g_W[OUTF * HARM];     // 512 KB, tf32-rounded fp32
__device__ __align__(16) __nv_bfloat16 g_Bh[HARM * INF];  // 64 KB basis hi
__device__ __align__(16) __nv_bfloat16 g_Bl[HARM * INF];  // 64 KB basis lo

__device__ __forceinline__ uint32_t smem_u32(const void* p) {
    uint32_t a;
    asm("{ .reg .u64 t; cvta.to.shared.u64 t, %1; cvt.u32.u64 %0, t; }"
        : "=r"(a) : "l"(p));
    return a;
}
__device__ __forceinline__ uint32_t pack_bf2(__nv_bfloat16 a, __nv_bfloat16 b) {
    return (uint32_t)__bfloat16_as_ushort(a) |
           ((uint32_t)__bfloat16_as_ushort(b) << 16);
}
__device__ __forceinline__ float tf32_rna(float v) {
    float r;
    asm("cvt.rna.tf32.f32 %0, %1;" : "=f"(r) : "f"(v));
    return r;
}

// ---------------------------------------------------------------------------
// Prep: W = tf32(amp*cos(phase)); basis bf16 hi/lo split for step 2.
// ---------------------------------------------------------------------------
__global__ void prep_kernel(const float* __restrict__ phase,
                            const float* __restrict__ amp,
                            const float* __restrict__ basis) {
    int idx = blockIdx.x * 256 + threadIdx.x;
    if (idx < OUTF * HARM) {
        g_W[idx] = tf32_rna(amp[idx] * cosf(phase[idx]));
    } else {
        int b = idx - OUTF * HARM;
        if (b < HARM * INF) {
            float v = basis[b];
            __nv_bfloat16 hi = __float2bfloat16(v);
            __nv_bfloat16 lo = __float2bfloat16(v - __bfloat162float(hi));
            g_Bh[b] = hi;
            g_Bl[b] = lo;
        }
    }
}

// ---------------------------------------------------------------------------
// Step 2: R = x @ basis^T via HMMA bf16 3-term split.
// 256 CTAs x 128 threads (4 warps). Tile 64 tokens x 32 harmonics,
// K chunks of 64 fp32. Epilogue: plain fp32 (tf32-rounded) to g_R.
// ---------------------------------------------------------------------------
#define RKC 64
__global__ __launch_bounds__(128) void resonance_hmma_kernel(
    const float* __restrict__ x) {
    __shared__ __nv_bfloat16 sxh[64 * RPAD];
    __shared__ __nv_bfloat16 sxl[64 * RPAD];
    __shared__ __nv_bfloat16 sbh[32 * RPAD];
    __shared__ __nv_bfloat16 sbl[32 * RPAD];

    int tid  = threadIdx.x;
    int lane = tid & 31;
    int wid  = tid >> 5;
    int tb   = blockIdx.x * 64;

    uint32_t sxh_b = smem_u32(sxh), sxl_b = smem_u32(sxl);
    uint32_t sbh_b = smem_u32(sbh), sbl_b = smem_u32(sbl);

    float acc[4][4];
#pragma unroll
    for (int j = 0; j < 4; j++)
#pragma unroll
        for (int c = 0; c < 4; c++) acc[j][c] = 0.0f;

    float4 xp[8];
    uint4  bhp[2], blp[2];
    {
        const float4* gx = reinterpret_cast<const float4*>(x);
#pragma unroll
        for (int r = 0; r < 8; r++) {
            int q = tid + r * 128;
            int row = q >> 4, c4 = q & 15;
            xp[r] = gx[(long)(tb + row) * (INF / 4) + c4];
        }
        const uint4* gbh = reinterpret_cast<const uint4*>(g_Bh);
        const uint4* gbl = reinterpret_cast<const uint4*>(g_Bl);
#pragma unroll
        for (int r = 0; r < 2; r++) {
            int q = tid + r * 128;
            int row = q >> 3, c4 = q & 7;
            bhp[r] = gbh[row * (INF / 8) + c4];
            blp[r] = gbl[row * (INF / 8) + c4];
        }
    }

    for (int ck = 0; ck < 16; ck++) {
        if (ck > 0) __syncthreads();
#pragma unroll
        for (int r = 0; r < 8; r++) {
            int q = tid + r * 128;
            int row = q >> 4, c4 = q & 15;
            float4 v = xp[r];
            __nv_bfloat16 h0 = __float2bfloat16(v.x);
            __nv_bfloat16 h1 = __float2bfloat16(v.y);
            __nv_bfloat16 h2 = __float2bfloat16(v.z);
            __nv_bfloat16 h3 = __float2bfloat16(v.w);
            uint2 hp = make_uint2(pack_bf2(h0, h1), pack_bf2(h2, h3));
            uint2 lp = make_uint2(
                pack_bf2(__float2bfloat16(v.x - __bfloat162float(h0)),
                         __float2bfloat16(v.y - __bfloat162float(h1))),
                pack_bf2(__float2bfloat16(v.z - __bfloat162float(h2)),
                         __float2bfloat16(v.w - __bfloat162float(h3))));
            int off = row * RPAD + c4 * 4;
            *reinterpret_cast<uint2*>(&sxh[off]) = hp;
            *reinterpret_cast<uint2*>(&sxl[off]) = lp;
        }
        {
            int row = tid >> 3, c4 = tid & 7;
            int off = row * RPAD + c4 * 8;
            *reinterpret_cast<uint4*>(&sbh[off]) = bhp[0];
            *reinterpret_cast<uint4*>(&sbl[off]) = blp[0];
            row = (tid + 128) >> 3; c4 = (tid + 128) & 7;
            off = row * RPAD + c4 * 8;
            *reinterpret_cast<uint4*>(&sbh[off]) = bhp[1];
            *reinterpret_cast<uint4*>(&sbl[off]) = blp[1];
        }
        __syncthreads();

        if (ck < 15) {
            int kc4 = (ck + 1) * 16;
            const float4* gx = reinterpret_cast<const float4*>(x);
#pragma unroll
            for (int r = 0; r < 8; r++) {
                int q = tid + r * 128;
                int row = q >> 4, c4 = q & 15;
                xp[r] = gx[(long)(tb + row) * (INF / 4) + kc4 + c4];
            }
            const uint4* gbh = reinterpret_cast<const uint4*>(g_Bh);
            const uint4* gbl = reinterpret_cast<const uint4*>(g_Bl);
#pragma unroll
            for (int r = 0; r < 2; r++) {
                int q = tid + r * 128;
                int row = q >> 3, c4 = q & 7;
                bhp[r] = gbh[row * (INF / 8) + (ck + 1) * 8 + c4];
                blp[r] = gbl[row * (INF / 8) + (ck + 1) * 8 + c4];
            }
        }

#pragma unroll
        for (int ks = 0; ks < 4; ks++) {
            int k0 = ks * 16;
            uint32_t ah[4], al[4];
            {
                int row = wid * 16 + (lane & 15);
                uint32_t ao = (uint32_t)row * (RPAD * 2) + k0 * 2 + (lane >> 4) * 16;
                asm volatile(
                    "ldmatrix.sync.aligned.m8n8.x4.shared.b16 {%0,%1,%2,%3}, [%4];"
                    : "=r"(ah[0]), "=r"(ah[1]), "=r"(ah[2]), "=r"(ah[3])
                    : "r"(sxh_b + ao));
                asm volatile(
                    "ldmatrix.sync.aligned.m8n8.x4.shared.b16 {%0,%1,%2,%3}, [%4];"
                    : "=r"(al[0]), "=r"(al[1]), "=r"(al[2]), "=r"(al[3])
                    : "r"(sxl_b + ao));
            }
#pragma unroll
            for (int j = 0; j < 4; j++) {
                int nrow = j * 8 + (lane & 7);
                uint32_t bo = (uint32_t)nrow * (RPAD * 2) + k0 * 2 + ((lane >> 3) & 1) * 16;
                uint32_t bh[2], bl[2];
                asm volatile(
                    "ldmatrix.sync.aligned.m8n8.x2.shared.b16 {%0,%1}, [%2];"
                    : "=r"(bh[0]), "=r"(bh[1]) : "r"(sbh_b + bo));
                asm volatile(
                    "ldmatrix.sync.aligned.m8n8.x2.shared.b16 {%0,%1}, [%2];"
                    : "=r"(bl[0]), "=r"(bl[1]) : "r"(sbl_b + bo));
                asm volatile(
                    "mma.sync.aligned.m16n8k16.row.col.f32.bf16.bf16.f32 "
                    "{%0,%1,%2,%3}, {%4,%5,%6,%7}, {%8,%9}, {%0,%1,%2,%3};"
                    : "+f"(acc[j][0]), "+f"(acc[j][1]), "+f"(acc[j][2]), "+f"(acc[j][3])
                    : "r"(ah[0]), "r"(ah[1]), "r"(ah[2]), "r"(ah[3]),
                      "r"(bh[0]), "r"(bh[1]));
                asm volatile(
                    "mma.sync.aligned.m16n8k16.row.col.f32.bf16.bf16.f32 "
                    "{%0,%1,%2,%3}, {%4,%5,%6,%7}, {%8,%9}, {%0,%1,%2,%3};"
                    : "+f"(acc[j][0]), "+f"(acc[j][1]), "+f"(acc[j][2]), "+f"(acc[j][3])
                    : "r"(al[0]), "r"(al[1]), "r"(al[2]), "r"(al[3]),
                      "r"(bh[0]), "r"(bh[1]));
                asm volatile(
                    "mma.sync.aligned.m16n8k16.row.col.f32.bf16.bf16.f32 "
                    "{%0,%1,%2,%3}, {%4,%5,%6,%7}, {%8,%9}, {%0,%1,%2,%3};"
                    : "+f"(acc[j][0]), "+f"(acc[j][1]), "+f"(acc[j][2]), "+f"(acc[j][3])
                    : "r"(ah[0]), "r"(ah[1]), "r"(ah[2]), "r"(ah[3]),
                      "r"(bl[0]), "r"(bl[1]));
            }
        }
    }

    // Epilogue: tf32-rounded fp32 R, coalesced float2 stores.
    int qrow = lane >> 2;
    int qcol = (lane & 3) * 2;
#pragma unroll
    for (int j = 0; j < 4; j++) {
#pragma unroll
        for (int hh = 0; hh < 2; hh++) {
            long t = tb + wid * 16 + qrow + hh * 8;
            float v0 = tf32_rna(acc[j][hh * 2 + 0]);
            float v1 = tf32_rna(acc[j][hh * 2 + 1]);
            *reinterpret_cast<float2*>(&g_R[t * HARM + j * 8 + qcol]) =
                make_float2(v0, v1);
        }
    }
}

// ---------------------------------------------------------------------------
// Step 3: out = R @ W^T via mma.m16n8k8 TF32, K=32 single term.
// CTA 128x128, 8 warps = 2(m) x 4(n), warp tile 64x32.
// Tiles 128 rows x 32 f32, pitch 36 f32 (144 B = 9x16B -> ldmatrix
// conflict-free). Staged epilogue through smem -> STG.128.
// ---------------------------------------------------------------------------
#define TPITCH 36                           // f32 words per row
#define TILE_BYTES (128 * TPITCH * 4)       // 18432
#define SM3_TOTAL (2 * TILE_BYTES)          // 36864 dynamic
#define WSTRIDE 40

__global__ __launch_bounds__(256) void holo_tf32_kernel(float* __restrict__ out) {
    extern __shared__ char smem[];
    __shared__ float wstage[8][16 * WSTRIDE];
    float* sA = reinterpret_cast<float*>(smem);
    float* sB = reinterpret_cast<float*>(smem + TILE_BYTES);

    int tid  = threadIdx.x;
    int lane = tid & 31;
    int wid  = tid >> 5;
    int warp_m = wid >> 2;   // 0..1
    int warp_n = wid & 3;    // 0..3

    int ob = blockIdx.x * 128;
    int tb = blockIdx.y * 128;

    // Fill tiles: 128 rows x 32 f32 = 8 x 16B chunks per row.
    const float4* gA = reinterpret_cast<const float4*>(&g_R[(long)tb * HARM]);
    const float4* gB = reinterpret_cast<const float4*>(&g_W[(long)ob * HARM]);
#pragma unroll
    for (int r = 0; r < 4; r++) {
        int q = tid + r * 256;        // 0..1023
        int row = q >> 3, ch = q & 7;
        *reinterpret_cast<float4*>(
            reinterpret_cast<char*>(sA) + row * (TPITCH * 4) + ch * 16) = gA[q];
        *reinterpret_cast<float4*>(
            reinterpret_cast<char*>(sB) + row * (TPITCH * 4) + ch * 16) = gB[q];
    }
    __syncthreads();

    uint32_t sAb = smem_u32(sA);
    uint32_t sBb = smem_u32(sB);

    float acc[4][4][4];
#pragma unroll
    for (int i = 0; i < 4; i++)
#pragma unroll
        for (int j = 0; j < 4; j++)
#pragma unroll
            for (int c = 0; c < 4; c++) acc[i][j][c] = 0.0f;

#pragma unroll
    for (int ks = 0; ks < 4; ks++) {
        // A fragments: m16k8 tf32 via ldmatrix.x4 (raw b16 bit-move).
        uint32_t af[4][4];
#pragma unroll
        for (int i = 0; i < 4; i++) {
            int row = warp_m * 64 + i * 16 + (lane & 15);
            uint32_t addr = sAb + (uint32_t)row * (TPITCH * 4) + ks * 32 + (lane >> 4) * 16;
            asm volatile(
                "ldmatrix.sync.aligned.m8n8.x4.shared.b16 {%0,%1,%2,%3}, [%4];"
                : "=r"(af[i][0]), "=r"(af[i][1]), "=r"(af[i][2]), "=r"(af[i][3])
                : "r"(addr));
        }
        // B fragments: k8n8 tf32 via ldmatrix.x2 on o-major rows.
        uint32_t bf[4][2];
#pragma unroll
        for (int j = 0; j < 4; j++) {
            int orow = warp_n * 32 + j * 8 + (lane & 7);
            uint32_t addr = sBb + (uint32_t)orow * (TPITCH * 4) + ks * 32 + ((lane >> 3) & 1) * 16;
            asm volatile(
                "ldmatrix.sync.aligned.m8n8.x2.shared.b16 {%0,%1}, [%2];"
                : "=r"(bf[j][0]), "=r"(bf[j][1])
                : "r"(addr));
        }
#pragma unroll
        for (int i = 0; i < 4; i++)
#pragma unroll
            for (int j = 0; j < 4; j++) {
                asm volatile(
                    "mma.sync.aligned.m16n8k8.row.col.f32.tf32.tf32.f32 "
                    "{%0,%1,%2,%3}, {%4,%5,%6,%7}, {%8,%9}, {%0,%1,%2,%3};"
                    : "+f"(acc[i][j][0]), "+f"(acc[i][j][1]),
                      "+f"(acc[i][j][2]), "+f"(acc[i][j][3])
                    : "r"(af[i][0]), "r"(af[i][1]), "r"(af[i][2]), "r"(af[i][3]),
                      "r"(bf[j][0]), "r"(bf[j][1]));
            }
    }

    // Staged epilogue: per-warp 16x32 tile through smem -> STG.128.
    int qrow = lane >> 2;
    int qcol = (lane & 3) * 2;
    float* wb = wstage[wid];
#pragma unroll
    for (int i = 0; i < 4; i++) {
#pragma unroll
        for (int j = 0; j < 4; j++) {
            *reinterpret_cast<float2*>(&wb[qrow * WSTRIDE + j * 8 + qcol]) =
                make_float2(acc[i][j][0], acc[i][j][1]);
            *reinterpret_cast<float2*>(&wb[(qrow + 8) * WSTRIDE + j * 8 + qcol]) =
                make_float2(acc[i][j][2], acc[i][j][3]);
        }
        __syncwarp();
        long r0 = tb + warp_m * 64 + i * 16;
        long c0 = ob + warp_n * 32;
#pragma unroll
        for (int s = 0; s < 4; s++) {
            int q = lane + s * 32;
            int row = q >> 3, c4 = q & 7;
            float4 v = *reinterpret_cast<float4*>(&wb[row * WSTRIDE + c4 * 4]);
            *reinterpret_cast<float4*>(&out[(r0 + row) * OUTF + c0 + c4 * 4]) = v;
        }
        __syncwarp();
    }
}

// ---------------------------------------------------------------------------
extern "C" void kernel_launch(void* const* d_in, const int* in_sizes, int n_in,
                              void* d_out, int out_size) {
    const float* x     = (const float*)d_in[0];  // [16384,1024]
    const float* basis = (const float*)d_in[1];  // [32,1024]
    const float* phase = (const float*)d_in[2];  // [4096,32]
    const float* amp   = (const float*)d_in[3];  // [4096,32]
    float* out = (float*)d_out;                  // [16384,4096]

    cudaFuncSetAttribute(holo_tf32_kernel,
                         cudaFuncAttributeMaxDynamicSharedMemorySize, SM3_TOTAL);

    int prep_items = OUTF * HARM + HARM * INF;
    prep_kernel<<<(prep_items + 255) / 256, 256>>>(phase, amp, basis);
    resonance_hmma_kernel<<<TOKENS / 64, 128>>>(x);
    dim3 gridC(OUTF / 128, TOKENS / 128);
    holo_tf32_kernel<<<gridC, 256, SM3_TOTAL>>>(out);
}

// round 7
// speedup vs baseline: 1.3661x; 1.0410x over previous
#include <cuda_runtime.h>
#include <cuda_bf16.h>
#include <cstdint>

// out[t][o] = sum_h R[t][h] * W[o][h],  R = x @ basis^T, W = amp*cos(phase)
// Step 2 (R): HMMA bf16 3-term split (error ~1e-5).
// Step 3 (out): mma.m16n8k8 TF32, single term K=32 (error ~2.7e-4 < 1e-3).
#define TOKENS 16384
#define INF    1024
#define HARM   32
#define OUTF   4096
#define RPAD   72    // step-2 staging row stride in bf16

// Scratch device globals
__device__ __align__(16) float g_R[TOKENS * HARM];   // 2 MB, tf32-rounded fp32
__device__ __align__(16) float g_W[OUTF * HARM];     // 512 KB, tf32-rounded fp32
__device__ __align__(16) __nv_bfloat16 g_Bh[HARM * INF];  // 64 KB basis hi
__device__ __align__(16) __nv_bfloat16 g_Bl[HARM * INF];  // 64 KB basis lo

__device__ __forceinline__ uint32_t smem_u32(const void* p) {
    uint32_t a;
    asm("{ .reg .u64 t; cvta.to.shared.u64 t, %1; cvt.u32.u64 %0, t; }"
        : "=r"(a) : "l"(p));
    return a;
}
__device__ __forceinline__ uint32_t pack_bf2(__nv_bfloat16 a, __nv_bfloat16 b) {
    return (uint32_t)__bfloat16_as_ushort(a) |
           ((uint32_t)__bfloat16_as_ushort(b) << 16);
}
__device__ __forceinline__ float tf32_rna(float v) {
    float r;
    asm("cvt.rna.tf32.f32 %0, %1;" : "=f"(r) : "f"(v));
    return r;
}

// ---------------------------------------------------------------------------
// Prep: W = tf32(amp*cos(phase)); basis bf16 hi/lo split for step 2.
// ---------------------------------------------------------------------------
__global__ void prep_kernel(const float* __restrict__ phase,
                            const float* __restrict__ amp,
                            const float* __restrict__ basis) {
    int idx = blockIdx.x * 256 + threadIdx.x;
    if (idx < OUTF * HARM) {
        g_W[idx] = tf32_rna(amp[idx] * cosf(phase[idx]));
    } else {
        int b = idx - OUTF * HARM;
        if (b < HARM * INF) {
            float v = basis[b];
            __nv_bfloat16 hi = __float2bfloat16(v);
            __nv_bfloat16 lo = __float2bfloat16(v - __bfloat162float(hi));
            g_Bh[b] = hi;
            g_Bl[b] = lo;
        }
    }
}

// ---------------------------------------------------------------------------
// Step 2: R = x @ basis^T via HMMA bf16 3-term split.
// 256 CTAs x 128 threads (4 warps). Tile 64 tokens x 32 harmonics,
// K chunks of 64 fp32. Epilogue: plain fp32 (tf32-rounded) to g_R.
// ---------------------------------------------------------------------------
__global__ __launch_bounds__(128) void resonance_hmma_kernel(
    const float* __restrict__ x) {
    __shared__ __nv_bfloat16 sxh[64 * RPAD];
    __shared__ __nv_bfloat16 sxl[64 * RPAD];
    __shared__ __nv_bfloat16 sbh[32 * RPAD];
    __shared__ __nv_bfloat16 sbl[32 * RPAD];

    int tid  = threadIdx.x;
    int lane = tid & 31;
    int wid  = tid >> 5;
    int tb   = blockIdx.x * 64;

    uint32_t sxh_b = smem_u32(sxh), sxl_b = smem_u32(sxl);
    uint32_t sbh_b = smem_u32(sbh), sbl_b = smem_u32(sbl);

    float acc[4][4];
#pragma unroll
    for (int j = 0; j < 4; j++)
#pragma unroll
        for (int c = 0; c < 4; c++) acc[j][c] = 0.0f;

    float4 xp[8];
    uint4  bhp[2], blp[2];
    {
        const float4* gx = reinterpret_cast<const float4*>(x);
#pragma unroll
        for (int r = 0; r < 8; r++) {
            int q = tid + r * 128;
            int row = q >> 4, c4 = q & 15;
            xp[r] = gx[(long)(tb + row) * (INF / 4) + c4];
        }
        const uint4* gbh = reinterpret_cast<const uint4*>(g_Bh);
        const uint4* gbl = reinterpret_cast<const uint4*>(g_Bl);
#pragma unroll
        for (int r = 0; r < 2; r++) {
            int q = tid + r * 128;
            int row = q >> 3, c4 = q & 7;
            bhp[r] = gbh[row * (INF / 8) + c4];
            blp[r] = gbl[row * (INF / 8) + c4];
        }
    }

    for (int ck = 0; ck < 16; ck++) {
        if (ck > 0) __syncthreads();
#pragma unroll
        for (int r = 0; r < 8; r++) {
            int q = tid + r * 128;
            int row = q >> 4, c4 = q & 15;
            float4 v = xp[r];
            __nv_bfloat16 h0 = __float2bfloat16(v.x);
            __nv_bfloat16 h1 = __float2bfloat16(v.y);
            __nv_bfloat16 h2 = __float2bfloat16(v.z);
            __nv_bfloat16 h3 = __float2bfloat16(v.w);
            uint2 hp = make_uint2(pack_bf2(h0, h1), pack_bf2(h2, h3));
            uint2 lp = make_uint2(
                pack_bf2(__float2bfloat16(v.x - __bfloat162float(h0)),
                         __float2bfloat16(v.y - __bfloat162float(h1))),
                pack_bf2(__float2bfloat16(v.z - __bfloat162float(h2)),
                         __float2bfloat16(v.w - __bfloat162float(h3))));
            int off = row * RPAD + c4 * 4;
            *reinterpret_cast<uint2*>(&sxh[off]) = hp;
            *reinterpret_cast<uint2*>(&sxl[off]) = lp;
        }
        {
            int row = tid >> 3, c4 = tid & 7;
            int off = row * RPAD + c4 * 8;
            *reinterpret_cast<uint4*>(&sbh[off]) = bhp[0];
            *reinterpret_cast<uint4*>(&sbl[off]) = blp[0];
            row = (tid + 128) >> 3; c4 = (tid + 128) & 7;
            off = row * RPAD + c4 * 8;
            *reinterpret_cast<uint4*>(&sbh[off]) = bhp[1];
            *reinterpret_cast<uint4*>(&sbl[off]) = blp[1];
        }
        __syncthreads();

        if (ck < 15) {
            int kc4 = (ck + 1) * 16;
            const float4* gx = reinterpret_cast<const float4*>(x);
#pragma unroll
            for (int r = 0; r < 8; r++) {
                int q = tid + r * 128;
                int row = q >> 4, c4 = q & 15;
                xp[r] = gx[(long)(tb + row) * (INF / 4) + kc4 + c4];
            }
            const uint4* gbh = reinterpret_cast<const uint4*>(g_Bh);
            const uint4* gbl = reinterpret_cast<const uint4*>(g_Bl);
#pragma unroll
            for (int r = 0; r < 2; r++) {
                int q = tid + r * 128;
                int row = q >> 3, c4 = q & 7;
                bhp[r] = gbh[row * (INF / 8) + (ck + 1) * 8 + c4];
                blp[r] = gbl[row * (INF / 8) + (ck + 1) * 8 + c4];
            }
        }

#pragma unroll
        for (int ks = 0; ks < 4; ks++) {
            int k0 = ks * 16;
            uint32_t ah[4], al[4];
            {
                int row = wid * 16 + (lane & 15);
                uint32_t ao = (uint32_t)row * (RPAD * 2) + k0 * 2 + (lane >> 4) * 16;
                asm volatile(
                    "ldmatrix.sync.aligned.m8n8.x4.shared.b16 {%0,%1,%2,%3}, [%4];"
                    : "=r"(ah[0]), "=r"(ah[1]), "=r"(ah[2]), "=r"(ah[3])
                    : "r"(sxh_b + ao));
                asm volatile(
                    "ldmatrix.sync.aligned.m8n8.x4.shared.b16 {%0,%1,%2,%3}, [%4];"
                    : "=r"(al[0]), "=r"(al[1]), "=r"(al[2]), "=r"(al[3])
                    : "r"(sxl_b + ao));
            }
#pragma unroll
            for (int j = 0; j < 4; j++) {
                int nrow = j * 8 + (lane & 7);
                uint32_t bo = (uint32_t)nrow * (RPAD * 2) + k0 * 2 + ((lane >> 3) & 1) * 16;
                uint32_t bh[2], bl[2];
                asm volatile(
                    "ldmatrix.sync.aligned.m8n8.x2.shared.b16 {%0,%1}, [%2];"
                    : "=r"(bh[0]), "=r"(bh[1]) : "r"(sbh_b + bo));
                asm volatile(
                    "ldmatrix.sync.aligned.m8n8.x2.shared.b16 {%0,%1}, [%2];"
                    : "=r"(bl[0]), "=r"(bl[1]) : "r"(sbl_b + bo));
                asm volatile(
                    "mma.sync.aligned.m16n8k16.row.col.f32.bf16.bf16.f32 "
                    "{%0,%1,%2,%3}, {%4,%5,%6,%7}, {%8,%9}, {%0,%1,%2,%3};"
                    : "+f"(acc[j][0]), "+f"(acc[j][1]), "+f"(acc[j][2]), "+f"(acc[j][3])
                    : "r"(ah[0]), "r"(ah[1]), "r"(ah[2]), "r"(ah[3]),
                      "r"(bh[0]), "r"(bh[1]));
                asm volatile(
                    "mma.sync.aligned.m16n8k16.row.col.f32.bf16.bf16.f32 "
                    "{%0,%1,%2,%3}, {%4,%5,%6,%7}, {%8,%9}, {%0,%1,%2,%3};"
                    : "+f"(acc[j][0]), "+f"(acc[j][1]), "+f"(acc[j][2]), "+f"(acc[j][3])
                    : "r"(al[0]), "r"(al[1]), "r"(al[2]), "r"(al[3]),
                      "r"(bh[0]), "r"(bh[1]));
                asm volatile(
                    "mma.sync.aligned.m16n8k16.row.col.f32.bf16.bf16.f32 "
                    "{%0,%1,%2,%3}, {%4,%5,%6,%7}, {%8,%9}, {%0,%1,%2,%3};"
                    : "+f"(acc[j][0]), "+f"(acc[j][1]), "+f"(acc[j][2]), "+f"(acc[j][3])
                    : "r"(ah[0]), "r"(ah[1]), "r"(ah[2]), "r"(ah[3]),
                      "r"(bl[0]), "r"(bl[1]));
            }
        }
    }

    int qrow = lane >> 2;
    int qcol = (lane & 3) * 2;
#pragma unroll
    for (int j = 0; j < 4; j++) {
#pragma unroll
        for (int hh = 0; hh < 2; hh++) {
            long t = tb + wid * 16 + qrow + hh * 8;
            float v0 = tf32_rna(acc[j][hh * 2 + 0]);
            float v1 = tf32_rna(acc[j][hh * 2 + 1]);
            *reinterpret_cast<float2*>(&g_R[t * HARM + j * 8 + qcol]) =
                make_float2(v0, v1);
        }
    }
}

// ---------------------------------------------------------------------------
// Step 3: out = R @ W^T via mma.m16n8k8 TF32, K=32 single term.
// CTA covers 128 tokens x 512 outputs as 4 B-subtiles (double-buffered).
// 8 warps = 2(m) x 4(n), warp tile 64x32 per subtile.
// Tiles 128 rows x 32 f32, pitch 36 f32. Staged epilogue -> __stcs STG.128.
// ---------------------------------------------------------------------------
#define TPITCH 36                           // f32 words per row
#define TILE_BYTES (128 * TPITCH * 4)       // 18432
#define SM3_TOTAL (3 * TILE_BYTES)          // A + 2 B buffers = 55296 dynamic
#define WSTRIDE 40
#define NBT 4

__global__ __launch_bounds__(256, 2) void holo_tf32_kernel(float* __restrict__ out) {
    extern __shared__ char smem[];
    __shared__ float wstage[8][16 * WSTRIDE];
    char* sA = smem;

    int tid  = threadIdx.x;
    int lane = tid & 31;
    int wid  = tid >> 5;
    int warp_m = wid >> 2;   // 0..1
    int warp_n = wid & 3;    // 0..3

    int ob0 = blockIdx.x * 512;
    int tb  = blockIdx.y * 128;

    const float4* gA = reinterpret_cast<const float4*>(&g_R[(long)tb * HARM]);
    const float4* gB = reinterpret_cast<const float4*>(&g_W[(long)ob0 * HARM]);

    // Fill A tile + B subtile 0: 1024 float4 each, 4 per thread.
#pragma unroll
    for (int r = 0; r < 4; r++) {
        int q = tid + r * 256;        // 0..1023
        int row = q >> 3, ch = q & 7;
        uint32_t soff = (uint32_t)row * (TPITCH * 4) + ch * 16;
        *reinterpret_cast<float4*>(sA + soff) = gA[q];
        *reinterpret_cast<float4*>(sA + TILE_BYTES + soff) = gB[q];
    }
    __syncthreads();

    uint32_t sAb = smem_u32(sA);
    int qrow = lane >> 2;
    int qcol = (lane & 3) * 2;

    for (int nb = 0; nb < NBT; nb++) {
        uint32_t sBb = sAb + TILE_BYTES + (uint32_t)(nb & 1) * TILE_BYTES;

        // Prefetch next B subtile into registers (overlaps mainloop).
        float4 bq[4];
        if (nb < NBT - 1) {
#pragma unroll
            for (int r = 0; r < 4; r++) {
                int q = tid + r * 256;
                bq[r] = gB[(nb + 1) * 1024 + q];
            }
        }

        float acc[4][4][4];
#pragma unroll
        for (int i = 0; i < 4; i++)
#pragma unroll
            for (int j = 0; j < 4; j++)
#pragma unroll
                for (int c = 0; c < 4; c++) acc[i][j][c] = 0.0f;

#pragma unroll
        for (int ks = 0; ks < 4; ks++) {
            uint32_t af[4][4];
#pragma unroll
            for (int i = 0; i < 4; i++) {
                int row = warp_m * 64 + i * 16 + (lane & 15);
                uint32_t addr = sAb + (uint32_t)row * (TPITCH * 4) + ks * 32 + (lane >> 4) * 16;
                asm volatile(
                    "ldmatrix.sync.aligned.m8n8.x4.shared.b16 {%0,%1,%2,%3}, [%4];"
                    : "=r"(af[i][0]), "=r"(af[i][1]), "=r"(af[i][2]), "=r"(af[i][3])
                    : "r"(addr));
            }
            uint32_t bf[4][2];
#pragma unroll
            for (int j = 0; j < 4; j++) {
                int orow = warp_n * 32 + j * 8 + (lane & 7);
                uint32_t addr = sBb + (uint32_t)orow * (TPITCH * 4) + ks * 32 + ((lane >> 3) & 1) * 16;
                asm volatile(
                    "ldmatrix.sync.aligned.m8n8.x2.shared.b16 {%0,%1}, [%2];"
                    : "=r"(bf[j][0]), "=r"(bf[j][1])
                    : "r"(addr));
            }
#pragma unroll
            for (int i = 0; i < 4; i++)
#pragma unroll
                for (int j = 0; j < 4; j++) {
                    asm volatile(
                        "mma.sync.aligned.m16n8k8.row.col.f32.tf32.tf32.f32 "
                        "{%0,%1,%2,%3}, {%4,%5,%6,%7}, {%8,%9}, {%0,%1,%2,%3};"
                        : "+f"(acc[i][j][0]), "+f"(acc[i][j][1]),
                          "+f"(acc[i][j][2]), "+f"(acc[i][j][3])
                        : "r"(af[i][0]), "r"(af[i][1]), "r"(af[i][2]), "r"(af[i][3]),
                          "r"(bf[j][0]), "r"(bf[j][1]));
                }
        }

        // Staged epilogue: per-warp 16x32 tile through smem -> streaming STG.128.
        float* wb = wstage[wid];
#pragma unroll
        for (int i = 0; i < 4; i++) {
#pragma unroll
            for (int j = 0; j < 4; j++) {
                *reinterpret_cast<float2*>(&wb[qrow * WSTRIDE + j * 8 + qcol]) =
                    make_float2(acc[i][j][0], acc[i][j][1]);
                *reinterpret_cast<float2*>(&wb[(qrow + 8) * WSTRIDE + j * 8 + qcol]) =
                    make_float2(acc[i][j][2], acc[i][j][3]);
            }
            __syncwarp();
            long r0 = tb + warp_m * 64 + i * 16;
            long c0 = ob0 + nb * 128 + warp_n * 32;
#pragma unroll
            for (int s = 0; s < 4; s++) {
                int q = lane + s * 32;
                int row = q >> 3, c4 = q & 7;
                float4 v = *reinterpret_cast<float4*>(&wb[row * WSTRIDE + c4 * 4]);
                __stcs(reinterpret_cast<float4*>(&out[(r0 + row) * OUTF + c0 + c4 * 4]), v);
            }
            __syncwarp();
        }

        // Commit prefetched B subtile into the other buffer.
        if (nb < NBT - 1) {
            uint32_t dst = TILE_BYTES + (uint32_t)((nb + 1) & 1) * TILE_BYTES;
#pragma unroll
            for (int r = 0; r < 4; r++) {
                int q = tid + r * 256;
                int row = q >> 3, ch = q & 7;
                *reinterpret_cast<float4*>(sA + dst + row * (TPITCH * 4) + ch * 16) = bq[r];
            }
            __syncthreads();
        }
    }
}

// ---------------------------------------------------------------------------
extern "C" void kernel_launch(void* const* d_in, const int* in_sizes, int n_in,
                              void* d_out, int out_size) {
    const float* x     = (const float*)d_in[0];  // [16384,1024]
    const float* basis = (const float*)d_in[1];  // [32,1024]
    const float* phase = (const float*)d_in[2];  // [4096,32]
    const float* amp   = (const float*)d_in[3];  // [4096,32]
    float* out = (float*)d_out;                  // [16384,4096]

    cudaFuncSetAttribute(holo_tf32_kernel,
                         cudaFuncAttributeMaxDynamicSharedMemorySize, SM3_TOTAL);

    int prep_items = OUTF * HARM + HARM * INF;
    prep_kernel<<<(prep_items + 255) / 256, 256>>>(phase, amp, basis);
    resonance_hmma_kernel<<<TOKENS / 64, 128>>>(x);
    dim3 gridC(OUTF / 512, TOKENS / 128);
    holo_tf32_kernel<<<gridC, 256, SM3_TOTAL>>>(out);
}

// round 8
// speedup vs baseline: 1.3709x; 1.0035x over previous
#include <cuda_runtime.h>
#include <cuda_bf16.h>
#include <cstdint>

// out[t][o] = sum_h R[t][h] * W[o][h],  R = x @ basis^T, W = amp*cos(phase)
// Step 2 (R): HMMA bf16 3-term split (error ~1e-5); basis split inline;
//             W prep folded into extra CTAs of the same launch.
// Step 3 (out): mma.m16n8k8 TF32, single term K=32 (error ~2.7e-4 < 1e-3).
#define TOKENS 16384
#define INF    1024
#define HARM   32
#define OUTF   4096
#define RPAD   72    // step-2 staging row stride in bf16

// Scratch device globals
__device__ __align__(16) float g_R[TOKENS * HARM];   // 2 MB, tf32-rounded fp32
__device__ __align__(16) float g_W[OUTF * HARM];     // 512 KB, tf32-rounded fp32

__device__ __forceinline__ uint32_t smem_u32(const void* p) {
    uint32_t a;
    asm("{ .reg .u64 t; cvta.to.shared.u64 t, %1; cvt.u32.u64 %0, t; }"
        : "=r"(a) : "l"(p));
    return a;
}
__device__ __forceinline__ uint32_t pack_bf2(__nv_bfloat16 a, __nv_bfloat16 b) {
    return (uint32_t)__bfloat16_as_ushort(a) |
           ((uint32_t)__bfloat16_as_ushort(b) << 16);
}
__device__ __forceinline__ float tf32_rna(float v) {
    float r;
    asm("cvt.rna.tf32.f32 %0, %1;" : "=f"(r) : "f"(v));
    return r;
}
__device__ __forceinline__ void split4(float4 v, uint2& hp, uint2& lp) {
    __nv_bfloat16 h0 = __float2bfloat16(v.x);
    __nv_bfloat16 h1 = __float2bfloat16(v.y);
    __nv_bfloat16 h2 = __float2bfloat16(v.z);
    __nv_bfloat16 h3 = __float2bfloat16(v.w);
    hp = make_uint2(pack_bf2(h0, h1), pack_bf2(h2, h3));
    lp = make_uint2(
        pack_bf2(__float2bfloat16(v.x - __bfloat162float(h0)),
                 __float2bfloat16(v.y - __bfloat162float(h1))),
        pack_bf2(__float2bfloat16(v.z - __bfloat162float(h2)),
                 __float2bfloat16(v.w - __bfloat162float(h3))));
}

// ---------------------------------------------------------------------------
// Step 2 (+W prep): CTAs [0,256) compute R = x @ basis^T via HMMA bf16
// 3-term split (basis split inline). CTAs [256,288) compute W = amp*cos(phase).
// ---------------------------------------------------------------------------
__global__ __launch_bounds__(128) void resonance_hmma_kernel(
    const float* __restrict__ x, const float* __restrict__ basis,
    const float* __restrict__ phase, const float* __restrict__ amp) {
    // ---- W-prep CTAs ----
    if (blockIdx.x >= 256) {
        int base = (blockIdx.x - 256) * 4096;
#pragma unroll
        for (int r = 0; r < 32; r++) {
            int idx = base + threadIdx.x + r * 128;
            g_W[idx] = tf32_rna(amp[idx] * cosf(phase[idx]));
        }
        return;
    }

    __shared__ __nv_bfloat16 sxh[64 * RPAD];
    __shared__ __nv_bfloat16 sxl[64 * RPAD];
    __shared__ __nv_bfloat16 sbh[32 * RPAD];
    __shared__ __nv_bfloat16 sbl[32 * RPAD];

    int tid  = threadIdx.x;
    int lane = tid & 31;
    int wid  = tid >> 5;
    int tb   = blockIdx.x * 64;

    uint32_t sxh_b = smem_u32(sxh), sxl_b = smem_u32(sxl);
    uint32_t sbh_b = smem_u32(sbh), sbl_b = smem_u32(sbl);

    float acc[4][4];
#pragma unroll
    for (int j = 0; j < 4; j++)
#pragma unroll
        for (int c = 0; c < 4; c++) acc[j][c] = 0.0f;

    const float4* gx = reinterpret_cast<const float4*>(x);
    const float4* gb = reinterpret_cast<const float4*>(basis);

    float4 xp[8], bp[4];
    // prefetch chunk 0: x 64x64 (1024 f4), basis 32x64 (512 f4)
#pragma unroll
    for (int r = 0; r < 8; r++) {
        int q = tid + r * 128;
        int row = q >> 4, c4 = q & 15;
        xp[r] = gx[(long)(tb + row) * (INF / 4) + c4];
    }
#pragma unroll
    for (int r = 0; r < 4; r++) {
        int q = tid + r * 128;
        int row = q >> 4, c4 = q & 15;
        bp[r] = gb[row * (INF / 4) + c4];
    }

    for (int ck = 0; ck < 16; ck++) {
        if (ck > 0) __syncthreads();
#pragma unroll
        for (int r = 0; r < 8; r++) {
            int q = tid + r * 128;
            int row = q >> 4, c4 = q & 15;
            uint2 hp, lp;
            split4(xp[r], hp, lp);
            int off = row * RPAD + c4 * 4;
            *reinterpret_cast<uint2*>(&sxh[off]) = hp;
            *reinterpret_cast<uint2*>(&sxl[off]) = lp;
        }
#pragma unroll
        for (int r = 0; r < 4; r++) {
            int q = tid + r * 128;
            int row = q >> 4, c4 = q & 15;
            uint2 hp, lp;
            split4(bp[r], hp, lp);
            int off = row * RPAD + c4 * 4;
            *reinterpret_cast<uint2*>(&sbh[off]) = hp;
            *reinterpret_cast<uint2*>(&sbl[off]) = lp;
        }
        __syncthreads();

        if (ck < 15) {
            int kc4 = (ck + 1) * 16;
#pragma unroll
            for (int r = 0; r < 8; r++) {
                int q = tid + r * 128;
                int row = q >> 4, c4 = q & 15;
                xp[r] = gx[(long)(tb + row) * (INF / 4) + kc4 + c4];
            }
#pragma unroll
            for (int r = 0; r < 4; r++) {
                int q = tid + r * 128;
                int row = q >> 4, c4 = q & 15;
                bp[r] = gb[row * (INF / 4) + kc4 + c4];
            }
        }

#pragma unroll
        for (int ks = 0; ks < 4; ks++) {
            int k0 = ks * 16;
            uint32_t ah[4], al[4];
            {
                int row = wid * 16 + (lane & 15);
                uint32_t ao = (uint32_t)row * (RPAD * 2) + k0 * 2 + (lane >> 4) * 16;
                asm volatile(
                    "ldmatrix.sync.aligned.m8n8.x4.shared.b16 {%0,%1,%2,%3}, [%4];"
                    : "=r"(ah[0]), "=r"(ah[1]), "=r"(ah[2]), "=r"(ah[3])
                    : "r"(sxh_b + ao));
                asm volatile(
                    "ldmatrix.sync.aligned.m8n8.x4.shared.b16 {%0,%1,%2,%3}, [%4];"
                    : "=r"(al[0]), "=r"(al[1]), "=r"(al[2]), "=r"(al[3])
                    : "r"(sxl_b + ao));
            }
#pragma unroll
            for (int j = 0; j < 4; j++) {
                int nrow = j * 8 + (lane & 7);
                uint32_t bo = (uint32_t)nrow * (RPAD * 2) + k0 * 2 + ((lane >> 3) & 1) * 16;
                uint32_t bh[2], bl[2];
                asm volatile(
                    "ldmatrix.sync.aligned.m8n8.x2.shared.b16 {%0,%1}, [%2];"
                    : "=r"(bh[0]), "=r"(bh[1]) : "r"(sbh_b + bo));
                asm volatile(
                    "ldmatrix.sync.aligned.m8n8.x2.shared.b16 {%0,%1}, [%2];"
                    : "=r"(bl[0]), "=r"(bl[1]) : "r"(sbl_b + bo));
                asm volatile(
                    "mma.sync.aligned.m16n8k16.row.col.f32.bf16.bf16.f32 "
                    "{%0,%1,%2,%3}, {%4,%5,%6,%7}, {%8,%9}, {%0,%1,%2,%3};"
                    : "+f"(acc[j][0]), "+f"(acc[j][1]), "+f"(acc[j][2]), "+f"(acc[j][3])
                    : "r"(ah[0]), "r"(ah[1]), "r"(ah[2]), "r"(ah[3]),
                      "r"(bh[0]), "r"(bh[1]));
                asm volatile(
                    "mma.sync.aligned.m16n8k16.row.col.f32.bf16.bf16.f32 "
                    "{%0,%1,%2,%3}, {%4,%5,%6,%7}, {%8,%9}, {%0,%1,%2,%3};"
                    : "+f"(acc[j][0]), "+f"(acc[j][1]), "+f"(acc[j][2]), "+f"(acc[j][3])
                    : "r"(al[0]), "r"(al[1]), "r"(al[2]), "r"(al[3]),
                      "r"(bh[0]), "r"(bh[1]));
                asm volatile(
                    "mma.sync.aligned.m16n8k16.row.col.f32.bf16.bf16.f32 "
                    "{%0,%1,%2,%3}, {%4,%5,%6,%7}, {%8,%9}, {%0,%1,%2,%3};"
                    : "+f"(acc[j][0]), "+f"(acc[j][1]), "+f"(acc[j][2]), "+f"(acc[j][3])
                    : "r"(ah[0]), "r"(ah[1]), "r"(ah[2]), "r"(ah[3]),
                      "r"(bl[0]), "r"(bl[1]));
            }
        }
    }

    int qrow = lane >> 2;
    int qcol = (lane & 3) * 2;
#pragma unroll
    for (int j = 0; j < 4; j++) {
#pragma unroll
        for (int hh = 0; hh < 2; hh++) {
            long t = tb + wid * 16 + qrow + hh * 8;
            float v0 = tf32_rna(acc[j][hh * 2 + 0]);
            float v1 = tf32_rna(acc[j][hh * 2 + 1]);
            *reinterpret_cast<float2*>(&g_R[t * HARM + j * 8 + qcol]) =
                make_float2(v0, v1);
        }
    }
}

// ---------------------------------------------------------------------------
// Step 3: out = R @ W^T via mma.m16n8k8 TF32, K=32 single term.
// CTA covers 128 tokens x 256 outputs (2 B-subtiles, loaded up-front).
// 8 warps = 2(m) x 4(n), warp tile 64x32 per subtile.
// Tiles 128 rows x 32 f32, pitch 36 f32. Staged epilogue -> __stcs STG.128.
// ---------------------------------------------------------------------------
#define TPITCH 36
#define TILE_BYTES (128 * TPITCH * 4)       // 18432
#define SM3_TOTAL (3 * TILE_BYTES)          // A + B0 + B1 = 55296
#define WSTRIDE 40
#define NBT 2

__global__ __launch_bounds__(256, 2) void holo_tf32_kernel(float* __restrict__ out) {
    extern __shared__ char smem[];
    __shared__ float wstage[8][16 * WSTRIDE];
    char* sA = smem;

    int tid  = threadIdx.x;
    int lane = tid & 31;
    int wid  = tid >> 5;
    int warp_m = wid >> 2;   // 0..1
    int warp_n = wid & 3;    // 0..3

    int ob0 = blockIdx.x * 256;
    int tb  = blockIdx.y * 128;

    const float4* gA = reinterpret_cast<const float4*>(&g_R[(long)tb * HARM]);
    const float4* gB = reinterpret_cast<const float4*>(&g_W[(long)ob0 * HARM]);

    // Fill A + both B subtiles: 3 x 1024 float4, 12 per thread.
#pragma unroll
    for (int r = 0; r < 4; r++) {
        int q = tid + r * 256;        // 0..1023
        int row = q >> 3, ch = q & 7;
        uint32_t soff = (uint32_t)row * (TPITCH * 4) + ch * 16;
        *reinterpret_cast<float4*>(sA + soff) = gA[q];
        *reinterpret_cast<float4*>(sA + TILE_BYTES + soff) = gB[q];
        *reinterpret_cast<float4*>(sA + 2 * TILE_BYTES + soff) = gB[1024 + q];
    }
    __syncthreads();

    uint32_t sAb = smem_u32(sA);
    int qrow = lane >> 2;
    int qcol = (lane & 3) * 2;

#pragma unroll
    for (int nb = 0; nb < NBT; nb++) {
        uint32_t sBb = sAb + TILE_BYTES + (uint32_t)nb * TILE_BYTES;

        float acc[4][4][4];
#pragma unroll
        for (int i = 0; i < 4; i++)
#pragma unroll
            for (int j = 0; j < 4; j++)
#pragma unroll
                for (int c = 0; c < 4; c++) acc[i][j][c] = 0.0f;

#pragma unroll
        for (int ks = 0; ks < 4; ks++) {
            uint32_t af[4][4];
#pragma unroll
            for (int i = 0; i < 4; i++) {
                int row = warp_m * 64 + i * 16 + (lane & 15);
                uint32_t addr = sAb + (uint32_t)row * (TPITCH * 4) + ks * 32 + (lane >> 4) * 16;
                asm volatile(
                    "ldmatrix.sync.aligned.m8n8.x4.shared.b16 {%0,%1,%2,%3}, [%4];"
                    : "=r"(af[i][0]), "=r"(af[i][1]), "=r"(af[i][2]), "=r"(af[i][3])
                    : "r"(addr));
            }
            uint32_t bf[4][2];
#pragma unroll
            for (int j = 0; j < 4; j++) {
                int orow = warp_n * 32 + j * 8 + (lane & 7);
                uint32_t addr = sBb + (uint32_t)orow * (TPITCH * 4) + ks * 32 + ((lane >> 3) & 1) * 16;
                asm volatile(
                    "ldmatrix.sync.aligned.m8n8.x2.shared.b16 {%0,%1}, [%2];"
                    : "=r"(bf[j][0]), "=r"(bf[j][1])
                    : "r"(addr));
            }
#pragma unroll
            for (int i = 0; i < 4; i++)
#pragma unroll
                for (int j = 0; j < 4; j++) {
                    asm volatile(
                        "mma.sync.aligned.m16n8k8.row.col.f32.tf32.tf32.f32 "
                        "{%0,%1,%2,%3}, {%4,%5,%6,%7}, {%8,%9}, {%0,%1,%2,%3};"
                        : "+f"(acc[i][j][0]), "+f"(acc[i][j][1]),
                          "+f"(acc[i][j][2]), "+f"(acc[i][j][3])
                        : "r"(af[i][0]), "r"(af[i][1]), "r"(af[i][2]), "r"(af[i][3]),
                          "r"(bf[j][0]), "r"(bf[j][1]));
                }
        }

        // Staged epilogue: per-warp 16x32 tile through smem -> streaming STG.128.
        float* wb = wstage[wid];
#pragma unroll
        for (int i = 0; i < 4; i++) {
#pragma unroll
            for (int j = 0; j < 4; j++) {
                *reinterpret_cast<float2*>(&wb[qrow * WSTRIDE + j * 8 + qcol]) =
                    make_float2(acc[i][j][0], acc[i][j][1]);
                *reinterpret_cast<float2*>(&wb[(qrow + 8) * WSTRIDE + j * 8 + qcol]) =
                    make_float2(acc[i][j][2], acc[i][j][3]);
            }
            __syncwarp();
            long r0 = tb + warp_m * 64 + i * 16;
            long c0 = ob0 + nb * 128 + warp_n * 32;
#pragma unroll
            for (int s = 0; s < 4; s++) {
                int q = lane + s * 32;
                int row = q >> 3, c4 = q & 7;
                float4 v = *reinterpret_cast<float4*>(&wb[row * WSTRIDE + c4 * 4]);
                __stcs(reinterpret_cast<float4*>(&out[(r0 + row) * OUTF + c0 + c4 * 4]), v);
            }
            __syncwarp();
        }
    }
}

// ---------------------------------------------------------------------------
extern "C" void kernel_launch(void* const* d_in, const int* in_sizes, int n_in,
                              void* d_out, int out_size) {
    const float* x     = (const float*)d_in[0];  // [16384,1024]
    const float* basis = (const float*)d_in[1];  // [32,1024]
    const float* phase = (const float*)d_in[2];  // [4096,32]
    const float* amp   = (const float*)d_in[3];  // [4096,32]
    float* out = (float*)d_out;                  // [16384,4096]

    cudaFuncSetAttribute(holo_tf32_kernel,
                         cudaFuncAttributeMaxDynamicSharedMemorySize, SM3_TOTAL);

    resonance_hmma_kernel<<<256 + 32, 128>>>(x, basis, phase, amp);
    dim3 gridC(OUTF / 256, TOKENS / 128);
    holo_tf32_kernel<<<gridC, 256, SM3_TOTAL>>>(out);
}

// round 9
// speedup vs baseline: 1.4801x; 1.0797x over previous
#include <cuda_runtime.h>
#include <cuda_bf16.h>
#include <cstdint>

// out[t][o] = sum_h R[t][h] * W[o][h],  R = x @ basis^T, W = amp*cos(phase)
// Step 2 (R): mma.m16n8k8 TF32 single term over K=1024 (error ~2e-4).
// Step 3 (out): mma.m16n8k8 TF32, single term K=32 (error ~2.7e-4).
// Combined ~3.4e-4 < 1e-3.
#define TOKENS 16384
#define INF    1024
#define HARM   32
#define OUTF   4096

// Scratch device globals
__device__ __align__(16) float g_R[TOKENS * HARM];   // 2 MB, tf32-rounded fp32
__device__ __align__(16) float g_W[OUTF * HARM];     // 512 KB, tf32-rounded fp32

__device__ __forceinline__ uint32_t smem_u32(const void* p) {
    uint32_t a;
    asm("{ .reg .u64 t; cvta.to.shared.u64 t, %1; cvt.u32.u64 %0, t; }"
        : "=r"(a) : "l"(p));
    return a;
}
__device__ __forceinline__ float tf32_rna(float v) {
    float r;
    asm("cvt.rna.tf32.f32 %0, %1;" : "=f"(r) : "f"(v));
    return r;
}
__device__ __forceinline__ uint32_t tf32_r(uint32_t v) {
    uint32_t r;
    asm("cvt.rna.tf32.f32 %0, %1;" : "=r"(r) : "r"(v));
    return r;
}

// ---------------------------------------------------------------------------
// Step 2 (+W prep): CTAs [0,256) compute R = x @ basis^T via TF32 mma.
// CTAs [256,288) compute W = tf32(amp*cos(phase)).
// Tile: 64 tokens x 32 harmonics, K chunks of 64 fp32, raw fp32 smem,
// pitch 68 floats (272 B -> conflict-free ldmatrix), cvt to tf32 on frags.
// ---------------------------------------------------------------------------
#define XPITCH 68
__global__ __launch_bounds__(128) void resonance_tf32_kernel(
    const float* __restrict__ x, const float* __restrict__ basis,
    const float* __restrict__ phase, const float* __restrict__ amp) {
    // ---- W-prep CTAs ----
    if (blockIdx.x >= 256) {
        int base = (blockIdx.x - 256) * 4096;
#pragma unroll
        for (int r = 0; r < 32; r++) {
            int idx = base + threadIdx.x + r * 128;
            g_W[idx] = tf32_rna(amp[idx] * cosf(phase[idx]));
        }
        return;
    }

    __shared__ float sx[64 * XPITCH];   // 17.4 KB
    __shared__ float sb[32 * XPITCH];   // 8.7 KB

    int tid  = threadIdx.x;
    int lane = tid & 31;
    int wid  = tid >> 5;        // warp -> 16-token m-tile
    int tb   = blockIdx.x * 64;

    uint32_t sx_b = smem_u32(sx), sb_b = smem_u32(sb);

    float acc[4][4];            // [jtile][frag]
#pragma unroll
    for (int j = 0; j < 4; j++)
#pragma unroll
        for (int c = 0; c < 4; c++) acc[j][c] = 0.0f;

    const float4* gx = reinterpret_cast<const float4*>(x);
    const float4* gb = reinterpret_cast<const float4*>(basis);

    float4 xp[8], bp[4];
    // prefetch chunk 0: x 64x64 (1024 f4, 8/thread), basis 32x64 (512 f4, 4/thread)
#pragma unroll
    for (int r = 0; r < 8; r++) {
        int q = tid + r * 128;
        int row = q >> 4, c4 = q & 15;
        xp[r] = gx[(long)(tb + row) * (INF / 4) + c4];
    }
#pragma unroll
    for (int r = 0; r < 4; r++) {
        int q = tid + r * 128;
        int row = q >> 4, c4 = q & 15;
        bp[r] = gb[row * (INF / 4) + c4];
    }

    for (int ck = 0; ck < 16; ck++) {
        if (ck > 0) __syncthreads();
        // commit raw fp32 chunks to smem (no conversion)
#pragma unroll
        for (int r = 0; r < 8; r++) {
            int q = tid + r * 128;
            int row = q >> 4, c4 = q & 15;
            *reinterpret_cast<float4*>(&sx[row * XPITCH + c4 * 4]) = xp[r];
        }
#pragma unroll
        for (int r = 0; r < 4; r++) {
            int q = tid + r * 128;
            int row = q >> 4, c4 = q & 15;
            *reinterpret_cast<float4*>(&sb[row * XPITCH + c4 * 4]) = bp[r];
        }
        __syncthreads();

        if (ck < 15) {
            int kc4 = (ck + 1) * 16;
#pragma unroll
            for (int r = 0; r < 8; r++) {
                int q = tid + r * 128;
                int row = q >> 4, c4 = q & 15;
                xp[r] = gx[(long)(tb + row) * (INF / 4) + kc4 + c4];
            }
#pragma unroll
            for (int r = 0; r < 4; r++) {
                int q = tid + r * 128;
                int row = q >> 4, c4 = q & 15;
                bp[r] = gb[row * (INF / 4) + kc4 + c4];
            }
        }

#pragma unroll
        for (int ks = 0; ks < 8; ks++) {
            // A fragments: m16k8, rows wid*16.., bit-moved via ldmatrix then cvt.
            uint32_t af[4];
            {
                int row = wid * 16 + (lane & 15);
                uint32_t ao = sx_b + (uint32_t)row * (XPITCH * 4) + ks * 32 + (lane >> 4) * 16;
                asm volatile(
                    "ldmatrix.sync.aligned.m8n8.x4.shared.b16 {%0,%1,%2,%3}, [%4];"
                    : "=r"(af[0]), "=r"(af[1]), "=r"(af[2]), "=r"(af[3])
                    : "r"(ao));
#pragma unroll
                for (int c = 0; c < 4; c++) af[c] = tf32_r(af[c]);
            }
#pragma unroll
            for (int j = 0; j < 4; j++) {
                int nrow = j * 8 + (lane & 7);
                uint32_t bo = sb_b + (uint32_t)nrow * (XPITCH * 4) + ks * 32 + ((lane >> 3) & 1) * 16;
                uint32_t bf[2];
                asm volatile(
                    "ldmatrix.sync.aligned.m8n8.x2.shared.b16 {%0,%1}, [%2];"
                    : "=r"(bf[0]), "=r"(bf[1]) : "r"(bo));
                bf[0] = tf32_r(bf[0]);
                bf[1] = tf32_r(bf[1]);
                asm volatile(
                    "mma.sync.aligned.m16n8k8.row.col.f32.tf32.tf32.f32 "
                    "{%0,%1,%2,%3}, {%4,%5,%6,%7}, {%8,%9}, {%0,%1,%2,%3};"
                    : "+f"(acc[j][0]), "+f"(acc[j][1]), "+f"(acc[j][2]), "+f"(acc[j][3])
                    : "r"(af[0]), "r"(af[1]), "r"(af[2]), "r"(af[3]),
                      "r"(bf[0]), "r"(bf[1]));
            }
        }
    }

    // Epilogue: tf32-rounded fp32 R, coalesced float2 stores.
    int qrow = lane >> 2;
    int qcol = (lane & 3) * 2;
#pragma unroll
    for (int j = 0; j < 4; j++) {
#pragma unroll
        for (int hh = 0; hh < 2; hh++) {
            long t = tb + wid * 16 + qrow + hh * 8;
            float v0 = tf32_rna(acc[j][hh * 2 + 0]);
            float v1 = tf32_rna(acc[j][hh * 2 + 1]);
            *reinterpret_cast<float2*>(&g_R[t * HARM + j * 8 + qcol]) =
                make_float2(v0, v1);
        }
    }
}

// ---------------------------------------------------------------------------
// Step 3: out = R @ W^T via mma.m16n8k8 TF32, K=32 single term.
// CTA covers 128 tokens x 256 outputs (2 B-subtiles, loaded up-front).
// 8 warps = 2(m) x 4(n), warp tile 64x32 per subtile.
// Tiles 128 rows x 32 f32, pitch 36 f32. Staged epilogue -> __stcs STG.128.
// (unchanged from R8 — measured 52.7us, L1-bound; attacked next round)
// ---------------------------------------------------------------------------
#define TPITCH 36
#define TILE_BYTES (128 * TPITCH * 4)       // 18432
#define SM3_TOTAL (3 * TILE_BYTES)          // A + B0 + B1 = 55296
#define WSTRIDE 40
#define NBT 2

__global__ __launch_bounds__(256, 2) void holo_tf32_kernel(float* __restrict__ out) {
    extern __shared__ char smem[];
    __shared__ float wstage[8][16 * WSTRIDE];
    char* sA = smem;

    int tid  = threadIdx.x;
    int lane = tid & 31;
    int wid  = tid >> 5;
    int warp_m = wid >> 2;   // 0..1
    int warp_n = wid & 3;    // 0..3

    int ob0 = blockIdx.x * 256;
    int tb  = blockIdx.y * 128;

    const float4* gA = reinterpret_cast<const float4*>(&g_R[(long)tb * HARM]);
    const float4* gB = reinterpret_cast<const float4*>(&g_W[(long)ob0 * HARM]);

#pragma unroll
    for (int r = 0; r < 4; r++) {
        int q = tid + r * 256;        // 0..1023
        int row = q >> 3, ch = q & 7;
        uint32_t soff = (uint32_t)row * (TPITCH * 4) + ch * 16;
        *reinterpret_cast<float4*>(sA + soff) = gA[q];
        *reinterpret_cast<float4*>(sA + TILE_BYTES + soff) = gB[q];
        *reinterpret_cast<float4*>(sA + 2 * TILE_BYTES + soff) = gB[1024 + q];
    }
    __syncthreads();

    uint32_t sAb = smem_u32(sA);
    int qrow = lane >> 2;
    int qcol = (lane & 3) * 2;

#pragma unroll
    for (int nb = 0; nb < NBT; nb++) {
        uint32_t sBb = sAb + TILE_BYTES + (uint32_t)nb * TILE_BYTES;

        float acc[4][4][4];
#pragma unroll
        for (int i = 0; i < 4; i++)
#pragma unroll
            for (int j = 0; j < 4; j++)
#pragma unroll
                for (int c = 0; c < 4; c++) acc[i][j][c] = 0.0f;

#pragma unroll
        for (int ks = 0; ks < 4; ks++) {
            uint32_t af[4][4];
#pragma unroll
            for (int i = 0; i < 4; i++) {
                int row = warp_m * 64 + i * 16 + (lane & 15);
                uint32_t addr = sAb + (uint32_t)row * (TPITCH * 4) + ks * 32 + (lane >> 4) * 16;
                asm volatile(
                    "ldmatrix.sync.aligned.m8n8.x4.shared.b16 {%0,%1,%2,%3}, [%4];"
                    : "=r"(af[i][0]), "=r"(af[i][1]), "=r"(af[i][2]), "=r"(af[i][3])
                    : "r"(addr));
            }
            uint32_t bf[4][2];
#pragma unroll
            for (int j = 0; j < 4; j++) {
                int orow = warp_n * 32 + j * 8 + (lane & 7);
                uint32_t addr = sBb + (uint32_t)orow * (TPITCH * 4) + ks * 32 + ((lane >> 3) & 1) * 16;
                asm volatile(
                    "ldmatrix.sync.aligned.m8n8.x2.shared.b16 {%0,%1}, [%2];"
                    : "=r"(bf[j][0]), "=r"(bf[j][1])
                    : "r"(addr));
            }
#pragma unroll
            for (int i = 0; i < 4; i++)
#pragma unroll
                for (int j = 0; j < 4; j++) {
                    asm volatile(
                        "mma.sync.aligned.m16n8k8.row.col.f32.tf32.tf32.f32 "
                        "{%0,%1,%2,%3}, {%4,%5,%6,%7}, {%8,%9}, {%0,%1,%2,%3};"
                        : "+f"(acc[i][j][0]), "+f"(acc[i][j][1]),
                          "+f"(acc[i][j][2]), "+f"(acc[i][j][3])
                        : "r"(af[i][0]), "r"(af[i][1]), "r"(af[i][2]), "r"(af[i][3]),
                          "r"(bf[j][0]), "r"(bf[j][1]));
                }
        }

        float* wb = wstage[wid];
#pragma unroll
        for (int i = 0; i < 4; i++) {
#pragma unroll
            for (int j = 0; j < 4; j++) {
                *reinterpret_cast<float2*>(&wb[qrow * WSTRIDE + j * 8 + qcol]) =
                    make_float2(acc[i][j][0], acc[i][j][1]);
                *reinterpret_cast<float2*>(&wb[(qrow + 8) * WSTRIDE + j * 8 + qcol]) =
                    make_float2(acc[i][j][2], acc[i][j][3]);
            }
            __syncwarp();
            long r0 = tb + warp_m * 64 + i * 16;
            long c0 = ob0 + nb * 128 + warp_n * 32;
#pragma unroll
            for (int s = 0; s < 4; s++) {
                int q = lane + s * 32;
                int row = q >> 3, c4 = q & 7;
                float4 v = *reinterpret_cast<float4*>(&wb[row * WSTRIDE + c4 * 4]);
                __stcs(reinterpret_cast<float4*>(&out[(r0 + row) * OUTF + c0 + c4 * 4]), v);
            }
            __syncwarp();
        }
    }
}

// ---------------------------------------------------------------------------
extern "C" void kernel_launch(void* const* d_in, const int* in_sizes, int n_in,
                              void* d_out, int out_size) {
    const float* x     = (const float*)d_in[0];  // [16384,1024]
    const float* basis = (const float*)d_in[1];  // [32,1024]
    const float* phase = (const float*)d_in[2];  // [4096,32]
    const float* amp   = (const float*)d_in[3];  // [4096,32]
    float* out = (float*)d_out;                  // [16384,4096]

    cudaFuncSetAttribute(holo_tf32_kernel,
                         cudaFuncAttributeMaxDynamicSharedMemorySize, SM3_TOTAL);

    resonance_tf32_kernel<<<256 + 32, 128>>>(x, basis, phase, amp);
    dim3 gridC(OUTF / 256, TOKENS / 128);
    holo_tf32_kernel<<<gridC, 256, SM3_TOTAL>>>(out);
}